// round 5
// baseline (speedup 1.0000x reference)
#include <cuda_runtime.h>

// DynamicFilterLayer2D: out[b,c,h,w] = sum_{i,j in 3x3} xpad[b,c,h+i,w+j] * f[b,c,i*3+j,h,w]
// B=8, C=32, H=256, W=256, K=3, zero pad 1.
// R4: 4x4 output patch per thread. Keeps stride-4-in-w warp coalescing (512B/instr,
// the thing R2 broke) while getting 4x MLP/ILP from the H dimension. x rows held in
// registers across the 3 vertical taps (6 row-loads instead of 12). Filters streamed
// with __ldcs (read-once, 604MB), out written with __stcs.

static constexpr int B = 8;
static constexpr int C = 32;
static constexpr int H = 256;
static constexpr int W = 256;
static constexpr int HW = H * W;
static constexpr int W4 = W / 4;   // 64
static constexpr int H4 = H / 4;   // 64

__global__ __launch_bounds__(256)
void dynamic_filter_kernel(const float* __restrict__ x,
                           const float* __restrict__ f,
                           float* __restrict__ out)
{
    int tid = blockIdx.x * blockDim.x + threadIdx.x;
    // total threads = B*C*H4*W4 = 1,048,576
    int w4 = tid & (W4 - 1);
    int t  = tid >> 6;
    int h4 = t & (H4 - 1);
    int bc = t >> 6;

    const int w0 = w4 * 4;
    const int h0 = h4 * 4;
    const long xbase = (long)bc * HW;
    const long fbase = (long)bc * 9 * HW;

    float acc[4][4];
    #pragma unroll
    for (int r = 0; r < 4; r++)
        #pragma unroll
        for (int k = 0; k < 4; k++) acc[r][k] = 0.f;

    // x rows needed: h0-1 .. h0+4. Row s contributes to output rows r = s-1, s, s+1
    // (within [0,3] of the patch) via tap i = s - r + 1.
    #pragma unroll
    for (int s = -1; s <= 4; s++) {
        const int hr = h0 + s;
        if (hr < 0 || hr >= H) continue;

        const float* xrow = x + xbase + (long)hr * W;
        const float4 cen = *reinterpret_cast<const float4*>(xrow + w0);
        float v[6];
        v[0] = (w0 > 0)     ? __ldg(xrow + w0 - 1) : 0.f;
        v[1] = cen.x; v[2] = cen.y; v[3] = cen.z; v[4] = cen.w;
        v[5] = (w0 + 4 < W) ? __ldg(xrow + w0 + 4) : 0.f;

        #pragma unroll
        for (int r = 0; r < 4; r++) {           // output row within patch
            const int i = s - r + 1;            // vertical tap
            if (i < 0 || i > 2) continue;       // compile-time prune
            const float* fp = f + fbase + (long)(i * 3) * HW + (long)(h0 + r) * W + w0;
            #pragma unroll
            for (int j = 0; j < 3; j++) {
                const float4 fv = __ldcs(reinterpret_cast<const float4*>(fp + (long)j * HW));
                acc[r][0] = fmaf(fv.x, v[0 + j], acc[r][0]);
                acc[r][1] = fmaf(fv.y, v[1 + j], acc[r][1]);
                acc[r][2] = fmaf(fv.z, v[2 + j], acc[r][2]);
                acc[r][3] = fmaf(fv.w, v[3 + j], acc[r][3]);
            }
        }
    }

    #pragma unroll
    for (int r = 0; r < 4; r++) {
        __stcs(reinterpret_cast<float4*>(out + xbase + (long)(h0 + r) * W + w0),
               make_float4(acc[r][0], acc[r][1], acc[r][2], acc[r][3]));
    }
}

extern "C" void kernel_launch(void* const* d_in, const int* in_sizes, int n_in,
                              void* d_out, int out_size)
{
    const float* x = (const float*)d_in[0];
    const float* f = (const float*)d_in[1];
    float* out = (float*)d_out;

    const int total = B * C * H4 * W4;   // 1,048,576 threads
    const int threads = 256;
    const int blocks = total / threads;  // 4096
    dynamic_filter_kernel<<<blocks, threads>>>(x, f, out);
}